// round 13
// baseline (speedup 1.0000x reference)
#include <cuda_runtime.h>
#include <math.h>
#include <stdint.h>

// Problem constants (fixed by the reference: B=8, T=4096, D=1024)
constexpr int Bb   = 8;
constexpr int Tt   = 4096;
constexpr int Dd   = 1024;
constexpr int Mtot = Bb * Tt;          // 32768 rows
constexpr int NC   = 32;               // scan chunks
constexpr int CL   = Tt / NC;          // 128 steps per chunk

// Scratch (device globals — no allocations allowed in kernel_launch)
__device__ float sc_u[(size_t)Mtot * Dd];
__device__ float sc_g[(size_t)Mtot * Dd];
__device__ float sc_h[(size_t)Mtot * Dd];    // written tf32-rounded by scan p3
__device__ float sc_wt[3][(size_t)Dd * Dd];  // Wi/Wg/Wo rounded (contiguous!)
__device__ float sc_bc[2 * Dd];              // concat(bi, bg)
__device__ float sc_P[Bb * NC * Dd];
__device__ float sc_S[Bb * NC * Dd];
__device__ float sc_C[Bb * NC * Dd];
__device__ int   sc_cnt[Bb * 4];             // p1->p2 fusion counters (self-reset)

__device__ __forceinline__ uint32_t f2tf(float x) {
    uint32_t r;
    asm("cvt.rna.tf32.f32 %0, %1;" : "=r"(r) : "f"(x));
    return r;
}
__device__ __forceinline__ float f2tf_f(float x) { return __uint_as_float(f2tf(x)); }
__device__ __forceinline__ uint32_t f2tf_bits(uint32_t bits) {
    return f2tf(__uint_as_float(bits));
}

// ---------------------------------------------------------------------------
// weights (y=0..2) + bias concat (y=3) in one launch
// ---------------------------------------------------------------------------
__global__ void round3_k(const float4* __restrict__ w0, const float4* __restrict__ w1,
                         const float4* __restrict__ w2,
                         const float4* __restrict__ b0, const float4* __restrict__ b1,
                         float4* __restrict__ o, float4* __restrict__ bc, int n4)
{
    if (blockIdx.y == 3) {
        if (blockIdx.x == 0) {
            for (int i = threadIdx.x; i < Dd / 4; i += blockDim.x) {
                bc[i] = b0[i];
                bc[Dd / 4 + i] = b1[i];
            }
        }
        return;
    }
    const float4* in = (blockIdx.y == 0) ? w0 : (blockIdx.y == 1) ? w1 : w2;
    float4* out = o + (size_t)blockIdx.y * n4;
    const int stride = gridDim.x * blockDim.x;
    for (int i = blockIdx.x * blockDim.x + threadIdx.x; i < n4; i += stride) {
        float4 v = in[i];
        out[i] = make_float4(f2tf_f(v.x), f2tf_f(v.y), f2tf_f(v.z), f2tf_f(v.w));
    }
}

// ===========================================================================
// tf32 mma.sync GEMM (R12-proven mainloop):
// CVTA=1: A is RAW fp32 (x) — A fragments rounded to tf32 in-loop (16 cvt/
//         warp/chunk, absorbed by idle alu pipe). B must be pre-rounded.
// CVTA=0: A already tf32-rounded in memory (h from scan p3).
// dual=1: W has 2048 rows (Wi||Wg), bias 2048; bn<8 -> C0 (no act),
//         bn>=8 -> C1 (sigmoid). dual=0: classic 1024-row GEMM into C0.
// CTA 128x128, BK=16, 8 warps @ 64x32, 3-stage cp.async, one barrier/chunk,
// ldmatrix fragments.
// ===========================================================================
constexpr int BM = 128, BN = 128, BK = 16;
constexpr int NCHUNK = Dd / BK;        // 64
constexpr int LDP    = BK + 4;         // padded row stride (floats)
constexpr int STGB   = BM * LDP * 4;   // stage bytes per matrix (10240)
constexpr int NSTG   = 3;
constexpr int SMEM_BYTES = 2 * NSTG * STGB;   // 61440

__device__ __forceinline__ uint32_t smem_u32(const void* p) {
    uint32_t a;
    asm("{ .reg .u64 t; cvta.to.shared.u64 t, %1; cvt.u32.u64 %0, t; }"
        : "=r"(a) : "l"(p));
    return a;
}
__device__ __forceinline__ void cp16(uint32_t s, const void* g) {
    asm volatile("cp.async.cg.shared.global [%0], [%1], 16;" :: "r"(s), "l"(g));
}
__device__ __forceinline__ void ldsm4(uint32_t& r0, uint32_t& r1, uint32_t& r2,
                                      uint32_t& r3, uint32_t addr) {
    asm volatile("ldmatrix.sync.aligned.m8n8.x4.shared.b16 {%0,%1,%2,%3}, [%4];"
                 : "=r"(r0), "=r"(r1), "=r"(r2), "=r"(r3) : "r"(addr));
}
__device__ __forceinline__ void mma8(float* d, const uint32_t* a, const uint32_t* b) {
    asm volatile(
        "mma.sync.aligned.m16n8k8.row.col.f32.tf32.tf32.f32 "
        "{%0,%1,%2,%3}, {%4,%5,%6,%7}, {%8,%9}, {%0,%1,%2,%3};"
        : "+f"(d[0]), "+f"(d[1]), "+f"(d[2]), "+f"(d[3])
        : "r"(a[0]), "r"(a[1]), "r"(a[2]), "r"(a[3]), "r"(b[0]), "r"(b[1]));
}

template <int CVTA>
__global__ __launch_bounds__(256, 2)
void gemm_tc(const float* __restrict__ A, const float* __restrict__ W,
             const float* __restrict__ bias, float* __restrict__ C0,
             float* __restrict__ C1, int dual)
{
    extern __shared__ float dynsm[];
    float* Asm = dynsm;                         // [NSTG][BM][LDP]
    float* Bsm = dynsm + NSTG * BM * LDP;       // [NSTG][BN][LDP]

    const int tid  = threadIdx.x;
    const int wid  = tid >> 5;
    const int lane = tid & 31;
    const int lr   = lane >> 2;          // 0..7
    const int lc   = lane & 3;           // 0..3
    const int bnb  = blockIdx.x;         // N tile (0..7 or 0..15)
    const int bmb  = blockIdx.y;         // M tile (0..255)

    const int act  = dual && (bnb >= 8);
    float* C       = (dual && bnb >= 8) ? C1 : C0;
    const int ncol = dual ? (bnb & 7) : bnb;     // output column tile

    const int wm = (wid >> 2) * 64;      // warp M offset in tile
    const int wn = (wid & 3) * 32;       // warp N offset in tile

    // ---- cp.async loader mapping ----
    const int r0 = tid >> 2,  q0 = tid & 3;
    const int r1 = r0 + 64;
    const float4* A4 = reinterpret_cast<const float4*>(A) + ((size_t)bmb * BM) * (Dd / 4);
    const float4* B4 = reinterpret_cast<const float4*>(W) + ((size_t)bnb * BN) * (Dd / 4);

    const uint32_t abase = smem_u32(Asm);
    const uint32_t bbase = smem_u32(Bsm);

    uint32_t sA0[NSTG], sA1[NSTG], sB0[NSTG], sB1[NSTG];
    #pragma unroll
    for (int s = 0; s < NSTG; s++) {
        sA0[s] = abase + ((s * BM + r0) * LDP + q0 * 4) * 4;
        sA1[s] = abase + ((s * BM + r1) * LDP + q0 * 4) * 4;
        sB0[s] = bbase + ((s * BN + r0) * LDP + q0 * 4) * 4;
        sB1[s] = bbase + ((s * BN + r1) * LDP + q0 * 4) * 4;
    }

    // ---- ldmatrix per-lane base addresses (stage 0) ----
    const uint32_t aFrag = abase + (((wm + (lane & 15)) * LDP + (lane >> 4) * 4) * 4);
    const uint32_t bFrag = bbase + (((wn + (lane & 7) + (lane >> 4) * 8) * LDP
                                     + ((lane >> 3) & 1) * 4) * 4);

    #define LOAD_STAGE(c, s) do {                                            \
        const float4* ga0 = A4 + (size_t)r0 * (Dd / 4) + (c) * 4 + q0;        \
        const float4* ga1 = A4 + (size_t)r1 * (Dd / 4) + (c) * 4 + q0;        \
        const float4* gb0 = B4 + (size_t)r0 * (Dd / 4) + (c) * 4 + q0;        \
        const float4* gb1 = B4 + (size_t)r1 * (Dd / 4) + (c) * 4 + q0;        \
        cp16(sA0[s], ga0); cp16(sA1[s], ga1);                                 \
        cp16(sB0[s], gb0); cp16(sB1[s], gb1);                                 \
        asm volatile("cp.async.commit_group;");                               \
    } while (0)

    float acc[4][4][4] = {};

    LOAD_STAGE(0, 0);
    LOAD_STAGE(1, 1);

    int s = 0;                 // stage of chunk c
    for (int c = 0; c < NCHUNK; c++) {
        if (c + 1 < NCHUNK) asm volatile("cp.async.wait_group 1;" ::: "memory");
        else                asm volatile("cp.async.wait_group 0;" ::: "memory");
        __syncthreads();   // stage c visible; stage c-1 consumed everywhere

        if (c + 2 < NCHUNK) {
            const int sn = (s + 2 >= NSTG) ? s + 2 - NSTG : s + 2;
            LOAD_STAGE(c + 2, sn);
        }

        const uint32_t aS = aFrag + (uint32_t)s * STGB;
        const uint32_t bS = bFrag + (uint32_t)s * STGB;

        #pragma unroll
        for (int ks = 0; ks < 2; ks++) {
            const uint32_t ko = (uint32_t)ks * 32;   // k0*4 bytes
            uint32_t af[4][4], bf[4][2];
            #pragma unroll
            for (int mi = 0; mi < 4; mi++) {
                ldsm4(af[mi][0], af[mi][1], af[mi][2], af[mi][3],
                      aS + (uint32_t)mi * (16 * LDP * 4) + ko);
                if (CVTA) {
                    af[mi][0] = f2tf_bits(af[mi][0]);
                    af[mi][1] = f2tf_bits(af[mi][1]);
                    af[mi][2] = f2tf_bits(af[mi][2]);
                    af[mi][3] = f2tf_bits(af[mi][3]);
                }
            }
            #pragma unroll
            for (int p = 0; p < 2; p++)
                ldsm4(bf[2 * p][0], bf[2 * p][1], bf[2 * p + 1][0], bf[2 * p + 1][1],
                      bS + (uint32_t)p * (16 * LDP * 4) + ko);
            #pragma unroll
            for (int mi = 0; mi < 4; mi++)
                #pragma unroll
                for (int ni = 0; ni < 4; ni++)
                    mma8(acc[mi][ni], af[mi], bf[ni]);
        }

        s = (s + 1 >= NSTG) ? 0 : s + 1;
    }

    // ---- epilogue: bias (+sigmoid), float2 stores ----
    #pragma unroll
    for (int ni = 0; ni < 4; ni++) {
        const int bcol = bnb * BN + wn + ni * 8 + lc * 2;     // into bias array
        const int gc   = ncol * BN + wn + ni * 8 + lc * 2;    // into C
        const float b0 = bias[bcol], b1 = bias[bcol + 1];
        #pragma unroll
        for (int mi = 0; mi < 4; mi++) {
            const size_t gr = (size_t)bmb * BM + wm + mi * 16 + lr;
            float v0 = acc[mi][ni][0] + b0;
            float v1 = acc[mi][ni][1] + b1;
            float v2 = acc[mi][ni][2] + b0;
            float v3 = acc[mi][ni][3] + b1;
            if (act) {
                v0 = 1.0f / (1.0f + __expf(-v0));
                v1 = 1.0f / (1.0f + __expf(-v1));
                v2 = 1.0f / (1.0f + __expf(-v2));
                v3 = 1.0f / (1.0f + __expf(-v3));
            }
            *reinterpret_cast<float2*>(C + gr * Dd + gc)       = make_float2(v0, v1);
            *reinterpret_cast<float2*>(C + (gr + 8) * Dd + gc) = make_float2(v2, v3);
        }
    }
    #undef LOAD_STAGE
}

// ---------------------------------------------------------------------------
// Scan phase 1+2 fused (SCALAR lanes, 1024 blocks — proven):
// per-(b,chunk,dblk) local pass; LAST block per (b,dblk) performs the
// 32-chunk serial combine inline. Counters self-reset for graph replay.
// ---------------------------------------------------------------------------
__global__ __launch_bounds__(256, 8)
void scan_p12()
{
    const int xb = blockIdx.x;                 // 0..3
    const int c  = blockIdx.y;                 // 0..31
    const int b  = blockIdx.z;                 // 0..7
    const int d  = xb * 256 + threadIdx.x;
    const size_t base = ((size_t)b * Tt + (size_t)c * CL) * Dd + d;

    float P = 1.0f, S = 0.0f;
    #pragma unroll 4
    for (int t = 0; t < CL; ++t) {
        const float gg = sc_g[base + (size_t)t * Dd];
        const float uu = sc_u[base + (size_t)t * Dd];
        S = fmaf(gg, S, (1.0f - gg) * uu);
        P *= gg;
    }
    const int idx = (b * NC + c) * Dd + d;
    sc_P[idx] = P;
    sc_S[idx] = S;

    __threadfence();
    __shared__ int lastf;
    if (threadIdx.x == 0)
        lastf = (atomicAdd(&sc_cnt[b * 4 + xb], 1) == NC - 1) ? 1 : 0;
    __syncthreads();

    if (lastf) {
        if (threadIdx.x == 0) sc_cnt[b * 4 + xb] = 0;   // reset for next replay
        __threadfence();
        float carry = 0.0f;
        #pragma unroll
        for (int c2 = 0; c2 < NC; ++c2) {
            const int k = (b * NC + c2) * Dd + d;
            sc_C[k] = carry;
            carry = fmaf(sc_P[k], carry, sc_S[k]);
        }
    }
}

// ---------------------------------------------------------------------------
// Scan phase 3 (SCALAR lanes, 1024 blocks — proven): replay each chunk from
// its carry-in, writing tf32-rounded h (h feeds only GEMM3).
// ---------------------------------------------------------------------------
__global__ void scan_phase3()
{
    const int d = blockIdx.x * blockDim.x + threadIdx.x;
    const int c = blockIdx.y;
    const int b = blockIdx.z;
    const size_t base = ((size_t)b * Tt + (size_t)c * CL) * Dd + d;

    float h = sc_C[(b * NC + c) * Dd + d];
    #pragma unroll 4
    for (int t = 0; t < CL; ++t) {
        const float gg = sc_g[base + (size_t)t * Dd];
        const float uu = sc_u[base + (size_t)t * Dd];
        h = fmaf(gg, h, (1.0f - gg) * uu);
        sc_h[base + (size_t)t * Dd] = f2tf_f(h);
    }
}

// ---------------------------------------------------------------------------
extern "C" void kernel_launch(void* const* d_in, const int* in_sizes, int n_in,
                              void* d_out, int out_size)
{
    (void)in_sizes; (void)n_in; (void)out_size;

    const float* x  = (const float*)d_in[0];
    const float* Wi = (const float*)d_in[1];
    const float* bi = (const float*)d_in[2];
    const float* Wg = (const float*)d_in[3];
    const float* bg = (const float*)d_in[4];
    const float* Wo = (const float*)d_in[5];
    const float* bo = (const float*)d_in[6];
    float* out = (float*)d_out;

    float *u, *g, *h, *wt, *bc;
    cudaGetSymbolAddress((void**)&u,  sc_u);
    cudaGetSymbolAddress((void**)&g,  sc_g);
    cudaGetSymbolAddress((void**)&h,  sc_h);
    cudaGetSymbolAddress((void**)&wt, sc_wt);
    cudaGetSymbolAddress((void**)&bc, sc_bc);
    float* wto = wt + 2 * (size_t)Dd * Dd;

    cudaFuncSetAttribute(gemm_tc<0>, cudaFuncAttributeMaxDynamicSharedMemorySize, SMEM_BYTES);
    cudaFuncSetAttribute(gemm_tc<1>, cudaFuncAttributeMaxDynamicSharedMemorySize, SMEM_BYTES);

    // pre-round weights to tf32 bits (+ bias concat); x is rounded in-GEMM
    round3_k<<<dim3(256, 4), 256>>>((const float4*)Wi, (const float4*)Wg,
                                    (const float4*)Wo, (const float4*)bi,
                                    (const float4*)bg, (float4*)wt, (float4*)bc,
                                    Dd * Dd / 4);

    // fused u+g GEMM: A = raw x (tf32-rounded in-loop), W = Wi||Wg, bias = bi||bg
    gemm_tc<1><<<dim3(16, Mtot / BM), 256, SMEM_BYTES>>>(x, wt, bc, u, g, 1);

    scan_p12<<<dim3(4, NC, Bb), 256>>>();
    scan_phase3<<<dim3(4, NC, Bb), 256>>>();

    // GEMM3: A = h (pre-rounded by scan p3)
    gemm_tc<0><<<dim3(8, Mtot / BM), 256, SMEM_BYTES>>>(h, wto, bo, out, nullptr, 0);
}

// round 14
// speedup vs baseline: 1.0098x; 1.0098x over previous
#include <cuda_runtime.h>
#include <math.h>
#include <stdint.h>

// Problem constants (fixed by the reference: B=8, T=4096, D=1024)
constexpr int Bb   = 8;
constexpr int Tt   = 4096;
constexpr int Dd   = 1024;
constexpr int Mtot = Bb * Tt;          // 32768 rows
constexpr int NC   = 64;               // scan chunks (R14: 32 -> 64)
constexpr int CL   = Tt / NC;          // 64 steps per chunk

// Scratch (device globals — no allocations allowed in kernel_launch)
__device__ float sc_u[(size_t)Mtot * Dd];
__device__ float sc_g[(size_t)Mtot * Dd];
__device__ float sc_h[(size_t)Mtot * Dd];    // written tf32-rounded by scan p3
__device__ float sc_xt[(size_t)Mtot * Dd];   // x rounded to tf32 bits
__device__ float sc_wt[3][(size_t)Dd * Dd];  // Wi/Wg/Wo rounded (contiguous!)
__device__ float sc_bc[2 * Dd];              // concat(bi, bg)
__device__ float sc_P[Bb * NC * Dd];
__device__ float sc_S[Bb * NC * Dd];
__device__ float sc_C[Bb * NC * Dd];
__device__ int   sc_cnt[Bb * 4];             // p1->p2 fusion counters (self-reset)

__device__ __forceinline__ uint32_t f2tf(float x) {
    uint32_t r;
    asm("cvt.rna.tf32.f32 %0, %1;" : "=r"(r) : "f"(x));
    return r;
}
__device__ __forceinline__ float f2tf_f(float x) { return __uint_as_float(f2tf(x)); }

// ---------------------------------------------------------------------------
// Pre-round fp32 -> tf32 bits (x)
// ---------------------------------------------------------------------------
__global__ void round_tf32_k(const float4* __restrict__ in, float4* __restrict__ out,
                             int n4)
{
    const int stride = gridDim.x * blockDim.x;
    for (int i = blockIdx.x * blockDim.x + threadIdx.x; i < n4; i += stride) {
        float4 v = in[i];
        out[i] = make_float4(f2tf_f(v.x), f2tf_f(v.y), f2tf_f(v.z), f2tf_f(v.w));
    }
}

// weights (y=0..2) + bias concat (y=3) in one launch
__global__ void round3_k(const float4* __restrict__ w0, const float4* __restrict__ w1,
                         const float4* __restrict__ w2,
                         const float4* __restrict__ b0, const float4* __restrict__ b1,
                         float4* __restrict__ o, float4* __restrict__ bc, int n4)
{
    if (blockIdx.y == 3) {
        if (blockIdx.x == 0) {
            for (int i = threadIdx.x; i < Dd / 4; i += blockDim.x) {
                bc[i] = b0[i];
                bc[Dd / 4 + i] = b1[i];
            }
        }
        return;
    }
    const float4* in = (blockIdx.y == 0) ? w0 : (blockIdx.y == 1) ? w1 : w2;
    float4* out = o + (size_t)blockIdx.y * n4;
    const int stride = gridDim.x * blockDim.x;
    for (int i = blockIdx.x * blockDim.x + threadIdx.x; i < n4; i += stride) {
        float4 v = in[i];
        out[i] = make_float4(f2tf_f(v.x), f2tf_f(v.y), f2tf_f(v.z), f2tf_f(v.w));
    }
}

// ===========================================================================
// tf32 mma.sync GEMM on PRE-ROUNDED operands (R12-proven, unchanged):
// dual=1: W has 2048 rows (Wi||Wg), bias 2048; bn<8 -> C0 (no act),
//         bn>=8 -> C1 (sigmoid). dual=0: classic 1024-row GEMM into C0.
// CTA 128x128, BK=16, 8 warps @ 64x32, 3-stage cp.async, one barrier/chunk,
// ldmatrix fragments, zero mainloop cvt.
// ===========================================================================
constexpr int BM = 128, BN = 128, BK = 16;
constexpr int NCHUNK = Dd / BK;        // 64
constexpr int LDP    = BK + 4;         // padded row stride (floats)
constexpr int STGB   = BM * LDP * 4;   // stage bytes per matrix (10240)
constexpr int NSTG   = 3;
constexpr int SMEM_BYTES = 2 * NSTG * STGB;   // 61440

__device__ __forceinline__ uint32_t smem_u32(const void* p) {
    uint32_t a;
    asm("{ .reg .u64 t; cvta.to.shared.u64 t, %1; cvt.u32.u64 %0, t; }"
        : "=r"(a) : "l"(p));
    return a;
}
__device__ __forceinline__ void cp16(uint32_t s, const void* g) {
    asm volatile("cp.async.cg.shared.global [%0], [%1], 16;" :: "r"(s), "l"(g));
}
__device__ __forceinline__ void ldsm4(uint32_t& r0, uint32_t& r1, uint32_t& r2,
                                      uint32_t& r3, uint32_t addr) {
    asm volatile("ldmatrix.sync.aligned.m8n8.x4.shared.b16 {%0,%1,%2,%3}, [%4];"
                 : "=r"(r0), "=r"(r1), "=r"(r2), "=r"(r3) : "r"(addr));
}
__device__ __forceinline__ void mma8(float* d, const uint32_t* a, const uint32_t* b) {
    asm volatile(
        "mma.sync.aligned.m16n8k8.row.col.f32.tf32.tf32.f32 "
        "{%0,%1,%2,%3}, {%4,%5,%6,%7}, {%8,%9}, {%0,%1,%2,%3};"
        : "+f"(d[0]), "+f"(d[1]), "+f"(d[2]), "+f"(d[3])
        : "r"(a[0]), "r"(a[1]), "r"(a[2]), "r"(a[3]), "r"(b[0]), "r"(b[1]));
}

__global__ __launch_bounds__(256, 2)
void gemm_tc(const float* __restrict__ A, const float* __restrict__ W,
             const float* __restrict__ bias, float* __restrict__ C0,
             float* __restrict__ C1, int dual)
{
    extern __shared__ float dynsm[];
    float* Asm = dynsm;                         // [NSTG][BM][LDP]
    float* Bsm = dynsm + NSTG * BM * LDP;       // [NSTG][BN][LDP]

    const int tid  = threadIdx.x;
    const int wid  = tid >> 5;
    const int lane = tid & 31;
    const int lr   = lane >> 2;          // 0..7
    const int lc   = lane & 3;           // 0..3
    const int bnb  = blockIdx.x;         // N tile (0..7 or 0..15)
    const int bmb  = blockIdx.y;         // M tile (0..255)

    const int act  = dual && (bnb >= 8);
    float* C       = (dual && bnb >= 8) ? C1 : C0;
    const int ncol = dual ? (bnb & 7) : bnb;     // output column tile

    const int wm = (wid >> 2) * 64;      // warp M offset in tile
    const int wn = (wid & 3) * 32;       // warp N offset in tile

    // ---- cp.async loader mapping ----
    const int r0 = tid >> 2,  q0 = tid & 3;
    const int r1 = r0 + 64;
    const float4* A4 = reinterpret_cast<const float4*>(A) + ((size_t)bmb * BM) * (Dd / 4);
    const float4* B4 = reinterpret_cast<const float4*>(W) + ((size_t)bnb * BN) * (Dd / 4);

    const uint32_t abase = smem_u32(Asm);
    const uint32_t bbase = smem_u32(Bsm);

    uint32_t sA0[NSTG], sA1[NSTG], sB0[NSTG], sB1[NSTG];
    #pragma unroll
    for (int s = 0; s < NSTG; s++) {
        sA0[s] = abase + ((s * BM + r0) * LDP + q0 * 4) * 4;
        sA1[s] = abase + ((s * BM + r1) * LDP + q0 * 4) * 4;
        sB0[s] = bbase + ((s * BN + r0) * LDP + q0 * 4) * 4;
        sB1[s] = bbase + ((s * BN + r1) * LDP + q0 * 4) * 4;
    }

    // ---- ldmatrix per-lane base addresses (stage 0) ----
    const uint32_t aFrag = abase + (((wm + (lane & 15)) * LDP + (lane >> 4) * 4) * 4);
    const uint32_t bFrag = bbase + (((wn + (lane & 7) + (lane >> 4) * 8) * LDP
                                     + ((lane >> 3) & 1) * 4) * 4);

    #define LOAD_STAGE(c, s) do {                                            \
        const float4* ga0 = A4 + (size_t)r0 * (Dd / 4) + (c) * 4 + q0;        \
        const float4* ga1 = A4 + (size_t)r1 * (Dd / 4) + (c) * 4 + q0;        \
        const float4* gb0 = B4 + (size_t)r0 * (Dd / 4) + (c) * 4 + q0;        \
        const float4* gb1 = B4 + (size_t)r1 * (Dd / 4) + (c) * 4 + q0;        \
        cp16(sA0[s], ga0); cp16(sA1[s], ga1);                                 \
        cp16(sB0[s], gb0); cp16(sB1[s], gb1);                                 \
        asm volatile("cp.async.commit_group;");                               \
    } while (0)

    float acc[4][4][4] = {};

    LOAD_STAGE(0, 0);
    LOAD_STAGE(1, 1);

    int s = 0;                 // stage of chunk c
    for (int c = 0; c < NCHUNK; c++) {
        if (c + 1 < NCHUNK) asm volatile("cp.async.wait_group 1;" ::: "memory");
        else                asm volatile("cp.async.wait_group 0;" ::: "memory");
        __syncthreads();   // stage c visible; stage c-1 consumed everywhere

        if (c + 2 < NCHUNK) {
            const int sn = (s + 2 >= NSTG) ? s + 2 - NSTG : s + 2;
            LOAD_STAGE(c + 2, sn);
        }

        const uint32_t aS = aFrag + (uint32_t)s * STGB;
        const uint32_t bS = bFrag + (uint32_t)s * STGB;

        #pragma unroll
        for (int ks = 0; ks < 2; ks++) {
            const uint32_t ko = (uint32_t)ks * 32;   // k0*4 bytes
            uint32_t af[4][4], bf[4][2];
            #pragma unroll
            for (int mi = 0; mi < 4; mi++)
                ldsm4(af[mi][0], af[mi][1], af[mi][2], af[mi][3],
                      aS + (uint32_t)mi * (16 * LDP * 4) + ko);
            #pragma unroll
            for (int p = 0; p < 2; p++)
                ldsm4(bf[2 * p][0], bf[2 * p][1], bf[2 * p + 1][0], bf[2 * p + 1][1],
                      bS + (uint32_t)p * (16 * LDP * 4) + ko);
            #pragma unroll
            for (int mi = 0; mi < 4; mi++)
                #pragma unroll
                for (int ni = 0; ni < 4; ni++)
                    mma8(acc[mi][ni], af[mi], bf[ni]);
        }

        s = (s + 1 >= NSTG) ? 0 : s + 1;
    }

    // ---- epilogue: bias (+sigmoid), float2 stores ----
    #pragma unroll
    for (int ni = 0; ni < 4; ni++) {
        const int bcol = bnb * BN + wn + ni * 8 + lc * 2;     // into bias array
        const int gc   = ncol * BN + wn + ni * 8 + lc * 2;    // into C
        const float b0 = bias[bcol], b1 = bias[bcol + 1];
        #pragma unroll
        for (int mi = 0; mi < 4; mi++) {
            const size_t gr = (size_t)bmb * BM + wm + mi * 16 + lr;
            float v0 = acc[mi][ni][0] + b0;
            float v1 = acc[mi][ni][1] + b1;
            float v2 = acc[mi][ni][2] + b0;
            float v3 = acc[mi][ni][3] + b1;
            if (act) {
                v0 = 1.0f / (1.0f + __expf(-v0));
                v1 = 1.0f / (1.0f + __expf(-v1));
                v2 = 1.0f / (1.0f + __expf(-v2));
                v3 = 1.0f / (1.0f + __expf(-v3));
            }
            *reinterpret_cast<float2*>(C + gr * Dd + gc)       = make_float2(v0, v1);
            *reinterpret_cast<float2*>(C + (gr + 8) * Dd + gc) = make_float2(v2, v3);
        }
    }
    #undef LOAD_STAGE
}

// ---------------------------------------------------------------------------
// Scan phase 1+2 fused (SCALAR lanes): NC=64 chunks of 64 steps -> 2048
// blocks (2x R12), halved serial chains. LAST block per (b,dblk) performs
// the 64-chunk serial combine inline. Counters self-reset for graph replay.
// ---------------------------------------------------------------------------
__global__ __launch_bounds__(256, 8)
void scan_p12()
{
    const int xb = blockIdx.x;                 // 0..3
    const int c  = blockIdx.y;                 // 0..63
    const int b  = blockIdx.z;                 // 0..7
    const int d  = xb * 256 + threadIdx.x;
    const size_t base = ((size_t)b * Tt + (size_t)c * CL) * Dd + d;

    float P = 1.0f, S = 0.0f;
    #pragma unroll 4
    for (int t = 0; t < CL; ++t) {
        const float gg = sc_g[base + (size_t)t * Dd];
        const float uu = sc_u[base + (size_t)t * Dd];
        S = fmaf(gg, S, (1.0f - gg) * uu);
        P *= gg;
    }
    const int idx = (b * NC + c) * Dd + d;
    sc_P[idx] = P;
    sc_S[idx] = S;

    __threadfence();
    __shared__ int lastf;
    if (threadIdx.x == 0)
        lastf = (atomicAdd(&sc_cnt[b * 4 + xb], 1) == NC - 1) ? 1 : 0;
    __syncthreads();

    if (lastf) {
        if (threadIdx.x == 0) sc_cnt[b * 4 + xb] = 0;   // reset for next replay
        __threadfence();
        float carry = 0.0f;
        #pragma unroll 8
        for (int c2 = 0; c2 < NC; ++c2) {
            const int k = (b * NC + c2) * Dd + d;
            sc_C[k] = carry;
            carry = fmaf(sc_P[k], carry, sc_S[k]);
        }
    }
}

// ---------------------------------------------------------------------------
// Scan phase 3 (SCALAR lanes, 2048 blocks): replay each 64-step chunk from
// its carry-in, writing tf32-rounded h (h feeds only GEMM3).
// ---------------------------------------------------------------------------
__global__ void scan_phase3()
{
    const int d = blockIdx.x * blockDim.x + threadIdx.x;
    const int c = blockIdx.y;
    const int b = blockIdx.z;
    const size_t base = ((size_t)b * Tt + (size_t)c * CL) * Dd + d;

    float h = sc_C[(b * NC + c) * Dd + d];
    #pragma unroll 4
    for (int t = 0; t < CL; ++t) {
        const float gg = sc_g[base + (size_t)t * Dd];
        const float uu = sc_u[base + (size_t)t * Dd];
        h = fmaf(gg, h, (1.0f - gg) * uu);
        sc_h[base + (size_t)t * Dd] = f2tf_f(h);
    }
}

// ---------------------------------------------------------------------------
extern "C" void kernel_launch(void* const* d_in, const int* in_sizes, int n_in,
                              void* d_out, int out_size)
{
    (void)in_sizes; (void)n_in; (void)out_size;

    const float* x  = (const float*)d_in[0];
    const float* Wi = (const float*)d_in[1];
    const float* bi = (const float*)d_in[2];
    const float* Wg = (const float*)d_in[3];
    const float* bg = (const float*)d_in[4];
    const float* Wo = (const float*)d_in[5];
    const float* bo = (const float*)d_in[6];
    float* out = (float*)d_out;

    float *u, *g, *h, *xt, *wt, *bc;
    cudaGetSymbolAddress((void**)&u,  sc_u);
    cudaGetSymbolAddress((void**)&g,  sc_g);
    cudaGetSymbolAddress((void**)&h,  sc_h);
    cudaGetSymbolAddress((void**)&xt, sc_xt);
    cudaGetSymbolAddress((void**)&wt, sc_wt);
    cudaGetSymbolAddress((void**)&bc, sc_bc);
    float* wto = wt + 2 * (size_t)Dd * Dd;

    cudaFuncSetAttribute(gemm_tc, cudaFuncAttributeMaxDynamicSharedMemorySize, SMEM_BYTES);

    // pre-round operands to tf32 bits (+ bias concat)
    round_tf32_k<<<4096, 256>>>((const float4*)x, (float4*)xt, Mtot * Dd / 4);
    round3_k<<<dim3(256, 4), 256>>>((const float4*)Wi, (const float4*)Wg,
                                    (const float4*)Wo, (const float4*)bi,
                                    (const float4*)bg, (float4*)wt, (float4*)bc,
                                    Dd * Dd / 4);

    // fused u+g GEMM: W = Wi||Wg (2048 rows), bias = bi||bg
    gemm_tc<<<dim3(16, Mtot / BM), 256, SMEM_BYTES>>>(xt, wt, bc, u, g, 1);

    scan_p12<<<dim3(4, NC, Bb), 256>>>();
    scan_phase3<<<dim3(4, NC, Bb), 256>>>();

    gemm_tc<<<dim3(8, Mtot / BM), 256, SMEM_BYTES>>>(h, wto, bo, out, nullptr, 0);
}

// round 15
// speedup vs baseline: 1.0222x; 1.0123x over previous
#include <cuda_runtime.h>
#include <math.h>
#include <stdint.h>

// Problem constants (fixed by the reference: B=8, T=4096, D=1024)
constexpr int Bb   = 8;
constexpr int Tt   = 4096;
constexpr int Dd   = 1024;
constexpr int Mtot = Bb * Tt;          // 32768 rows
constexpr int NC   = 32;               // scan chunks (R12-proven)
constexpr int CL   = Tt / NC;          // 128 steps per chunk

// Scratch (device globals — no allocations allowed in kernel_launch)
__device__ float sc_u[(size_t)Mtot * Dd];
__device__ float sc_g[(size_t)Mtot * Dd];
__device__ float sc_h[(size_t)Mtot * Dd];    // written tf32-rounded by scan p3
__device__ float sc_xt[(size_t)Mtot * Dd];   // x rounded to tf32 bits
__device__ float sc_wt[3][(size_t)Dd * Dd];  // Wi/Wg/Wo rounded (contiguous!)
__device__ float sc_bc[2 * Dd];              // concat(bi, bg)
__device__ float sc_P[Bb * NC * Dd];
__device__ float sc_S[Bb * NC * Dd];
__device__ float sc_C[Bb * NC * Dd];
__device__ int   sc_cnt[Bb * 4];             // p1->p2 fusion counters (self-reset)

__device__ __forceinline__ uint32_t f2tf(float x) {
    uint32_t r;
    asm("cvt.rna.tf32.f32 %0, %1;" : "=r"(r) : "f"(x));
    return r;
}
__device__ __forceinline__ float f2tf_f(float x) { return __uint_as_float(f2tf(x)); }

// ---------------------------------------------------------------------------
// Pre-round fp32 -> tf32 bits (x)
// ---------------------------------------------------------------------------
__global__ void round_tf32_k(const float4* __restrict__ in, float4* __restrict__ out,
                             int n4)
{
    const int stride = gridDim.x * blockDim.x;
    for (int i = blockIdx.x * blockDim.x + threadIdx.x; i < n4; i += stride) {
        float4 v = in[i];
        out[i] = make_float4(f2tf_f(v.x), f2tf_f(v.y), f2tf_f(v.z), f2tf_f(v.w));
    }
}

// weights (y=0..2) + bias concat (y=3) in one launch
__global__ void round3_k(const float4* __restrict__ w0, const float4* __restrict__ w1,
                         const float4* __restrict__ w2,
                         const float4* __restrict__ b0, const float4* __restrict__ b1,
                         float4* __restrict__ o, float4* __restrict__ bc, int n4)
{
    if (blockIdx.y == 3) {
        if (blockIdx.x == 0) {
            for (int i = threadIdx.x; i < Dd / 4; i += blockDim.x) {
                bc[i] = b0[i];
                bc[Dd / 4 + i] = b1[i];
            }
        }
        return;
    }
    const float4* in = (blockIdx.y == 0) ? w0 : (blockIdx.y == 1) ? w1 : w2;
    float4* out = o + (size_t)blockIdx.y * n4;
    const int stride = gridDim.x * blockDim.x;
    for (int i = blockIdx.x * blockDim.x + threadIdx.x; i < n4; i += stride) {
        float4 v = in[i];
        out[i] = make_float4(f2tf_f(v.x), f2tf_f(v.y), f2tf_f(v.z), f2tf_f(v.w));
    }
}

// ===========================================================================
// tf32 mma.sync GEMM on PRE-ROUNDED operands (R12-proven, unchanged):
// dual=1: W has 2048 rows (Wi||Wg), bias 2048; bn<8 -> C0 (no act),
//         bn>=8 -> C1 (sigmoid). dual=0: classic 1024-row GEMM into C0.
// CTA 128x128, BK=16, 8 warps @ 64x32, 3-stage cp.async, one barrier/chunk,
// ldmatrix fragments, zero mainloop cvt.
// ===========================================================================
constexpr int BM = 128, BN = 128, BK = 16;
constexpr int NCHUNK = Dd / BK;        // 64
constexpr int LDP    = BK + 4;         // padded row stride (floats)
constexpr int STGB   = BM * LDP * 4;   // stage bytes per matrix (10240)
constexpr int NSTG   = 3;
constexpr int SMEM_BYTES = 2 * NSTG * STGB;   // 61440

__device__ __forceinline__ uint32_t smem_u32(const void* p) {
    uint32_t a;
    asm("{ .reg .u64 t; cvta.to.shared.u64 t, %1; cvt.u32.u64 %0, t; }"
        : "=r"(a) : "l"(p));
    return a;
}
__device__ __forceinline__ void cp16(uint32_t s, const void* g) {
    asm volatile("cp.async.cg.shared.global [%0], [%1], 16;" :: "r"(s), "l"(g));
}
__device__ __forceinline__ void ldsm4(uint32_t& r0, uint32_t& r1, uint32_t& r2,
                                      uint32_t& r3, uint32_t addr) {
    asm volatile("ldmatrix.sync.aligned.m8n8.x4.shared.b16 {%0,%1,%2,%3}, [%4];"
                 : "=r"(r0), "=r"(r1), "=r"(r2), "=r"(r3) : "r"(addr));
}
__device__ __forceinline__ void mma8(float* d, const uint32_t* a, const uint32_t* b) {
    asm volatile(
        "mma.sync.aligned.m16n8k8.row.col.f32.tf32.tf32.f32 "
        "{%0,%1,%2,%3}, {%4,%5,%6,%7}, {%8,%9}, {%0,%1,%2,%3};"
        : "+f"(d[0]), "+f"(d[1]), "+f"(d[2]), "+f"(d[3])
        : "r"(a[0]), "r"(a[1]), "r"(a[2]), "r"(a[3]), "r"(b[0]), "r"(b[1]));
}

__global__ __launch_bounds__(256, 2)
void gemm_tc(const float* __restrict__ A, const float* __restrict__ W,
             const float* __restrict__ bias, float* __restrict__ C0,
             float* __restrict__ C1, int dual)
{
    extern __shared__ float dynsm[];
    float* Asm = dynsm;                         // [NSTG][BM][LDP]
    float* Bsm = dynsm + NSTG * BM * LDP;       // [NSTG][BN][LDP]

    const int tid  = threadIdx.x;
    const int wid  = tid >> 5;
    const int lane = tid & 31;
    const int lr   = lane >> 2;          // 0..7
    const int lc   = lane & 3;           // 0..3
    const int bnb  = blockIdx.x;         // N tile (0..7 or 0..15)
    const int bmb  = blockIdx.y;         // M tile (0..255)

    const int act  = dual && (bnb >= 8);
    float* C       = (dual && bnb >= 8) ? C1 : C0;
    const int ncol = dual ? (bnb & 7) : bnb;     // output column tile

    const int wm = (wid >> 2) * 64;      // warp M offset in tile
    const int wn = (wid & 3) * 32;       // warp N offset in tile

    // ---- cp.async loader mapping ----
    const int r0 = tid >> 2,  q0 = tid & 3;
    const int r1 = r0 + 64;
    const float4* A4 = reinterpret_cast<const float4*>(A) + ((size_t)bmb * BM) * (Dd / 4);
    const float4* B4 = reinterpret_cast<const float4*>(W) + ((size_t)bnb * BN) * (Dd / 4);

    const uint32_t abase = smem_u32(Asm);
    const uint32_t bbase = smem_u32(Bsm);

    uint32_t sA0[NSTG], sA1[NSTG], sB0[NSTG], sB1[NSTG];
    #pragma unroll
    for (int s = 0; s < NSTG; s++) {
        sA0[s] = abase + ((s * BM + r0) * LDP + q0 * 4) * 4;
        sA1[s] = abase + ((s * BM + r1) * LDP + q0 * 4) * 4;
        sB0[s] = bbase + ((s * BN + r0) * LDP + q0 * 4) * 4;
        sB1[s] = bbase + ((s * BN + r1) * LDP + q0 * 4) * 4;
    }

    // ---- ldmatrix per-lane base addresses (stage 0) ----
    const uint32_t aFrag = abase + (((wm + (lane & 15)) * LDP + (lane >> 4) * 4) * 4);
    const uint32_t bFrag = bbase + (((wn + (lane & 7) + (lane >> 4) * 8) * LDP
                                     + ((lane >> 3) & 1) * 4) * 4);

    #define LOAD_STAGE(c, s) do {                                            \
        const float4* ga0 = A4 + (size_t)r0 * (Dd / 4) + (c) * 4 + q0;        \
        const float4* ga1 = A4 + (size_t)r1 * (Dd / 4) + (c) * 4 + q0;        \
        const float4* gb0 = B4 + (size_t)r0 * (Dd / 4) + (c) * 4 + q0;        \
        const float4* gb1 = B4 + (size_t)r1 * (Dd / 4) + (c) * 4 + q0;        \
        cp16(sA0[s], ga0); cp16(sA1[s], ga1);                                 \
        cp16(sB0[s], gb0); cp16(sB1[s], gb1);                                 \
        asm volatile("cp.async.commit_group;");                               \
    } while (0)

    float acc[4][4][4] = {};

    LOAD_STAGE(0, 0);
    LOAD_STAGE(1, 1);

    int s = 0;                 // stage of chunk c
    for (int c = 0; c < NCHUNK; c++) {
        if (c + 1 < NCHUNK) asm volatile("cp.async.wait_group 1;" ::: "memory");
        else                asm volatile("cp.async.wait_group 0;" ::: "memory");
        __syncthreads();   // stage c visible; stage c-1 consumed everywhere

        if (c + 2 < NCHUNK) {
            const int sn = (s + 2 >= NSTG) ? s + 2 - NSTG : s + 2;
            LOAD_STAGE(c + 2, sn);
        }

        const uint32_t aS = aFrag + (uint32_t)s * STGB;
        const uint32_t bS = bFrag + (uint32_t)s * STGB;

        #pragma unroll
        for (int ks = 0; ks < 2; ks++) {
            const uint32_t ko = (uint32_t)ks * 32;   // k0*4 bytes
            uint32_t af[4][4], bf[4][2];
            #pragma unroll
            for (int mi = 0; mi < 4; mi++)
                ldsm4(af[mi][0], af[mi][1], af[mi][2], af[mi][3],
                      aS + (uint32_t)mi * (16 * LDP * 4) + ko);
            #pragma unroll
            for (int p = 0; p < 2; p++)
                ldsm4(bf[2 * p][0], bf[2 * p][1], bf[2 * p + 1][0], bf[2 * p + 1][1],
                      bS + (uint32_t)p * (16 * LDP * 4) + ko);
            #pragma unroll
            for (int mi = 0; mi < 4; mi++)
                #pragma unroll
                for (int ni = 0; ni < 4; ni++)
                    mma8(acc[mi][ni], af[mi], bf[ni]);
        }

        s = (s + 1 >= NSTG) ? 0 : s + 1;
    }

    // ---- epilogue: bias (+sigmoid), float2 stores ----
    #pragma unroll
    for (int ni = 0; ni < 4; ni++) {
        const int bcol = bnb * BN + wn + ni * 8 + lc * 2;     // into bias array
        const int gc   = ncol * BN + wn + ni * 8 + lc * 2;    // into C
        const float b0 = bias[bcol], b1 = bias[bcol + 1];
        #pragma unroll
        for (int mi = 0; mi < 4; mi++) {
            const size_t gr = (size_t)bmb * BM + wm + mi * 16 + lr;
            float v0 = acc[mi][ni][0] + b0;
            float v1 = acc[mi][ni][1] + b1;
            float v2 = acc[mi][ni][2] + b0;
            float v3 = acc[mi][ni][3] + b1;
            if (act) {
                v0 = 1.0f / (1.0f + __expf(-v0));
                v1 = 1.0f / (1.0f + __expf(-v1));
                v2 = 1.0f / (1.0f + __expf(-v2));
                v3 = 1.0f / (1.0f + __expf(-v3));
            }
            *reinterpret_cast<float2*>(C + gr * Dd + gc)       = make_float2(v0, v1);
            *reinterpret_cast<float2*>(C + (gr + 8) * Dd + gc) = make_float2(v2, v3);
        }
    }
    #undef LOAD_STAGE
}

// ---------------------------------------------------------------------------
// Scan phase 1+2 fused (SCALAR lanes, 1024 blocks — R12-proven), with DEEPER
// UNROLL (16) to raise outstanding loads: loads across t are independent;
// only the S fma chain is serial.
// ---------------------------------------------------------------------------
__global__ __launch_bounds__(256, 8)
void scan_p12()
{
    const int xb = blockIdx.x;                 // 0..3
    const int c  = blockIdx.y;                 // 0..31
    const int b  = blockIdx.z;                 // 0..7
    const int d  = xb * 256 + threadIdx.x;
    const size_t base = ((size_t)b * Tt + (size_t)c * CL) * Dd + d;

    float P = 1.0f, S = 0.0f;
    #pragma unroll 16
    for (int t = 0; t < CL; ++t) {
        const float gg = sc_g[base + (size_t)t * Dd];
        const float uu = sc_u[base + (size_t)t * Dd];
        S = fmaf(gg, S, (1.0f - gg) * uu);
        P *= gg;
    }
    const int idx = (b * NC + c) * Dd + d;
    sc_P[idx] = P;
    sc_S[idx] = S;

    __threadfence();
    __shared__ int lastf;
    if (threadIdx.x == 0)
        lastf = (atomicAdd(&sc_cnt[b * 4 + xb], 1) == NC - 1) ? 1 : 0;
    __syncthreads();

    if (lastf) {
        if (threadIdx.x == 0) sc_cnt[b * 4 + xb] = 0;   // reset for next replay
        __threadfence();
        float carry = 0.0f;
        #pragma unroll
        for (int c2 = 0; c2 < NC; ++c2) {
            const int k = (b * NC + c2) * Dd + d;
            sc_C[k] = carry;
            carry = fmaf(sc_P[k], carry, sc_S[k]);
        }
    }
}

// ---------------------------------------------------------------------------
// Scan phase 3 (SCALAR lanes, 1024 blocks — R12-proven), deeper unroll (16):
// replay each chunk from its carry-in, writing tf32-rounded h.
// ---------------------------------------------------------------------------
__global__ void scan_phase3()
{
    const int d = blockIdx.x * blockDim.x + threadIdx.x;
    const int c = blockIdx.y;
    const int b = blockIdx.z;
    const size_t base = ((size_t)b * Tt + (size_t)c * CL) * Dd + d;

    float h = sc_C[(b * NC + c) * Dd + d];
    #pragma unroll 16
    for (int t = 0; t < CL; ++t) {
        const float gg = sc_g[base + (size_t)t * Dd];
        const float uu = sc_u[base + (size_t)t * Dd];
        h = fmaf(gg, h, (1.0f - gg) * uu);
        sc_h[base + (size_t)t * Dd] = f2tf_f(h);
    }
}

// ---------------------------------------------------------------------------
extern "C" void kernel_launch(void* const* d_in, const int* in_sizes, int n_in,
                              void* d_out, int out_size)
{
    (void)in_sizes; (void)n_in; (void)out_size;

    const float* x  = (const float*)d_in[0];
    const float* Wi = (const float*)d_in[1];
    const float* bi = (const float*)d_in[2];
    const float* Wg = (const float*)d_in[3];
    const float* bg = (const float*)d_in[4];
    const float* Wo = (const float*)d_in[5];
    const float* bo = (const float*)d_in[6];
    float* out = (float*)d_out;

    float *u, *g, *h, *xt, *wt, *bc;
    cudaGetSymbolAddress((void**)&u,  sc_u);
    cudaGetSymbolAddress((void**)&g,  sc_g);
    cudaGetSymbolAddress((void**)&h,  sc_h);
    cudaGetSymbolAddress((void**)&xt, sc_xt);
    cudaGetSymbolAddress((void**)&wt, sc_wt);
    cudaGetSymbolAddress((void**)&bc, sc_bc);
    float* wto = wt + 2 * (size_t)Dd * Dd;

    cudaFuncSetAttribute(gemm_tc, cudaFuncAttributeMaxDynamicSharedMemorySize, SMEM_BYTES);

    // pre-round operands to tf32 bits (+ bias concat)
    round_tf32_k<<<4096, 256>>>((const float4*)x, (float4*)xt, Mtot * Dd / 4);
    round3_k<<<dim3(256, 4), 256>>>((const float4*)Wi, (const float4*)Wg,
                                    (const float4*)Wo, (const float4*)bi,
                                    (const float4*)bg, (float4*)wt, (float4*)bc,
                                    Dd * Dd / 4);

    // fused u+g GEMM: W = Wi||Wg (2048 rows), bias = bi||bg
    gemm_tc<<<dim3(16, Mtot / BM), 256, SMEM_BYTES>>>(xt, wt, bc, u, g, 1);

    scan_p12<<<dim3(4, NC, Bb), 256>>>();
    scan_phase3<<<dim3(4, NC, Bb), 256>>>();

    gemm_tc<<<dim3(8, Mtot / BM), 256, SMEM_BYTES>>>(h, wto, bo, out, nullptr, 0);
}

// round 16
// speedup vs baseline: 1.0258x; 1.0035x over previous
#include <cuda_runtime.h>
#include <math.h>
#include <stdint.h>

// Problem constants (fixed by the reference: B=8, T=4096, D=1024)
constexpr int Bb   = 8;
constexpr int Tt   = 4096;
constexpr int Dd   = 1024;
constexpr int Mtot = Bb * Tt;          // 32768 rows
constexpr int NC   = 32;               // scan chunks (R12-proven)
constexpr int CL   = Tt / NC;          // 128 steps per chunk

// Scratch (device globals — no allocations allowed in kernel_launch)
__device__ float sc_u[(size_t)Mtot * Dd];
__device__ float sc_g[(size_t)Mtot * Dd];
__device__ float sc_h[(size_t)Mtot * Dd];    // written tf32-rounded by scan p3
__device__ float sc_xt[(size_t)Mtot * Dd];   // x rounded to tf32 bits
__device__ float sc_wt[3][(size_t)Dd * Dd];  // Wi/Wg/Wo rounded (contiguous!)
__device__ float sc_bc[2 * Dd];              // concat(bi, bg)
__device__ float sc_P[Bb * NC * Dd];
__device__ float sc_S[Bb * NC * Dd];
__device__ float sc_C[Bb * NC * Dd];
__device__ int   sc_cnt[Bb * 4];             // p1->p2 fusion counters (self-reset)

__device__ __forceinline__ uint32_t f2tf(float x) {
    uint32_t r;
    asm("cvt.rna.tf32.f32 %0, %1;" : "=r"(r) : "f"(x));
    return r;
}
__device__ __forceinline__ float f2tf_f(float x) { return __uint_as_float(f2tf(x)); }

// ---------------------------------------------------------------------------
// Unified prologue rounding: ONE launch rounds x (blocks [0,4096)), the three
// weight matrices (blocks [4096,4864), 256 each) and copies the bias concat
// (block 4864). All sections are DRAM-parallel.
// ---------------------------------------------------------------------------
constexpr int XBLK = 4096;
constexpr int WBLK = 256;

__global__ void round_all_k(const float4* __restrict__ x,
                            const float4* __restrict__ w0,
                            const float4* __restrict__ w1,
                            const float4* __restrict__ w2,
                            const float4* __restrict__ b0,
                            const float4* __restrict__ b1,
                            float4* __restrict__ xt,
                            float4* __restrict__ wt,
                            float4* __restrict__ bc)
{
    const int bx = blockIdx.x;
    const int n4w = Dd * Dd / 4;

    if (bx < XBLK) {                       // ---- x rounding ----
        const int n4 = Mtot * Dd / 4;
        const int stride = XBLK * 256;
        for (int i = bx * 256 + threadIdx.x; i < n4; i += stride) {
            float4 v = x[i];
            xt[i] = make_float4(f2tf_f(v.x), f2tf_f(v.y), f2tf_f(v.z), f2tf_f(v.w));
        }
    } else if (bx < XBLK + 3 * WBLK) {     // ---- weight rounding ----
        const int wsel = (bx - XBLK) / WBLK;          // 0..2
        const int wb   = (bx - XBLK) % WBLK;          // block within matrix
        const float4* in = (wsel == 0) ? w0 : (wsel == 1) ? w1 : w2;
        float4* out = wt + (size_t)wsel * n4w;
        const int stride = WBLK * 256;
        for (int i = wb * 256 + threadIdx.x; i < n4w; i += stride) {
            float4 v = in[i];
            out[i] = make_float4(f2tf_f(v.x), f2tf_f(v.y), f2tf_f(v.z), f2tf_f(v.w));
        }
    } else {                               // ---- bias concat ----
        for (int i = threadIdx.x; i < Dd / 4; i += blockDim.x) {
            bc[i] = b0[i];
            bc[Dd / 4 + i] = b1[i];
        }
    }
}

// ===========================================================================
// tf32 mma.sync GEMM on PRE-ROUNDED operands (R12-proven, unchanged):
// dual=1: W has 2048 rows (Wi||Wg), bias 2048; bn<8 -> C0 (no act),
//         bn>=8 -> C1 (sigmoid). dual=0: classic 1024-row GEMM into C0.
// CTA 128x128, BK=16, 8 warps @ 64x32, 3-stage cp.async, one barrier/chunk,
// ldmatrix fragments, zero mainloop cvt.
// ===========================================================================
constexpr int BM = 128, BN = 128, BK = 16;
constexpr int NCHUNK = Dd / BK;        // 64
constexpr int LDP    = BK + 4;         // padded row stride (floats)
constexpr int STGB   = BM * LDP * 4;   // stage bytes per matrix (10240)
constexpr int NSTG   = 3;
constexpr int SMEM_BYTES = 2 * NSTG * STGB;   // 61440

__device__ __forceinline__ uint32_t smem_u32(const void* p) {
    uint32_t a;
    asm("{ .reg .u64 t; cvta.to.shared.u64 t, %1; cvt.u32.u64 %0, t; }"
        : "=r"(a) : "l"(p));
    return a;
}
__device__ __forceinline__ void cp16(uint32_t s, const void* g) {
    asm volatile("cp.async.cg.shared.global [%0], [%1], 16;" :: "r"(s), "l"(g));
}
__device__ __forceinline__ void ldsm4(uint32_t& r0, uint32_t& r1, uint32_t& r2,
                                      uint32_t& r3, uint32_t addr) {
    asm volatile("ldmatrix.sync.aligned.m8n8.x4.shared.b16 {%0,%1,%2,%3}, [%4];"
                 : "=r"(r0), "=r"(r1), "=r"(r2), "=r"(r3) : "r"(addr));
}
__device__ __forceinline__ void mma8(float* d, const uint32_t* a, const uint32_t* b) {
    asm volatile(
        "mma.sync.aligned.m16n8k8.row.col.f32.tf32.tf32.f32 "
        "{%0,%1,%2,%3}, {%4,%5,%6,%7}, {%8,%9}, {%0,%1,%2,%3};"
        : "+f"(d[0]), "+f"(d[1]), "+f"(d[2]), "+f"(d[3])
        : "r"(a[0]), "r"(a[1]), "r"(a[2]), "r"(a[3]), "r"(b[0]), "r"(b[1]));
}

__global__ __launch_bounds__(256, 2)
void gemm_tc(const float* __restrict__ A, const float* __restrict__ W,
             const float* __restrict__ bias, float* __restrict__ C0,
             float* __restrict__ C1, int dual)
{
    extern __shared__ float dynsm[];
    float* Asm = dynsm;                         // [NSTG][BM][LDP]
    float* Bsm = dynsm + NSTG * BM * LDP;       // [NSTG][BN][LDP]

    const int tid  = threadIdx.x;
    const int wid  = tid >> 5;
    const int lane = tid & 31;
    const int lr   = lane >> 2;          // 0..7
    const int lc   = lane & 3;           // 0..3
    const int bnb  = blockIdx.x;         // N tile (0..7 or 0..15)
    const int bmb  = blockIdx.y;         // M tile (0..255)

    const int act  = dual && (bnb >= 8);
    float* C       = (dual && bnb >= 8) ? C1 : C0;
    const int ncol = dual ? (bnb & 7) : bnb;     // output column tile

    const int wm = (wid >> 2) * 64;      // warp M offset in tile
    const int wn = (wid & 3) * 32;       // warp N offset in tile

    // ---- cp.async loader mapping ----
    const int r0 = tid >> 2,  q0 = tid & 3;
    const int r1 = r0 + 64;
    const float4* A4 = reinterpret_cast<const float4*>(A) + ((size_t)bmb * BM) * (Dd / 4);
    const float4* B4 = reinterpret_cast<const float4*>(W) + ((size_t)bnb * BN) * (Dd / 4);

    const uint32_t abase = smem_u32(Asm);
    const uint32_t bbase = smem_u32(Bsm);

    uint32_t sA0[NSTG], sA1[NSTG], sB0[NSTG], sB1[NSTG];
    #pragma unroll
    for (int s = 0; s < NSTG; s++) {
        sA0[s] = abase + ((s * BM + r0) * LDP + q0 * 4) * 4;
        sA1[s] = abase + ((s * BM + r1) * LDP + q0 * 4) * 4;
        sB0[s] = bbase + ((s * BN + r0) * LDP + q0 * 4) * 4;
        sB1[s] = bbase + ((s * BN + r1) * LDP + q0 * 4) * 4;
    }

    // ---- ldmatrix per-lane base addresses (stage 0) ----
    const uint32_t aFrag = abase + (((wm + (lane & 15)) * LDP + (lane >> 4) * 4) * 4);
    const uint32_t bFrag = bbase + (((wn + (lane & 7) + (lane >> 4) * 8) * LDP
                                     + ((lane >> 3) & 1) * 4) * 4);

    #define LOAD_STAGE(c, s) do {                                            \
        const float4* ga0 = A4 + (size_t)r0 * (Dd / 4) + (c) * 4 + q0;        \
        const float4* ga1 = A4 + (size_t)r1 * (Dd / 4) + (c) * 4 + q0;        \
        const float4* gb0 = B4 + (size_t)r0 * (Dd / 4) + (c) * 4 + q0;        \
        const float4* gb1 = B4 + (size_t)r1 * (Dd / 4) + (c) * 4 + q0;        \
        cp16(sA0[s], ga0); cp16(sA1[s], ga1);                                 \
        cp16(sB0[s], gb0); cp16(sB1[s], gb1);                                 \
        asm volatile("cp.async.commit_group;");                               \
    } while (0)

    float acc[4][4][4] = {};

    LOAD_STAGE(0, 0);
    LOAD_STAGE(1, 1);

    int s = 0;                 // stage of chunk c
    for (int c = 0; c < NCHUNK; c++) {
        if (c + 1 < NCHUNK) asm volatile("cp.async.wait_group 1;" ::: "memory");
        else                asm volatile("cp.async.wait_group 0;" ::: "memory");
        __syncthreads();   // stage c visible; stage c-1 consumed everywhere

        if (c + 2 < NCHUNK) {
            const int sn = (s + 2 >= NSTG) ? s + 2 - NSTG : s + 2;
            LOAD_STAGE(c + 2, sn);
        }

        const uint32_t aS = aFrag + (uint32_t)s * STGB;
        const uint32_t bS = bFrag + (uint32_t)s * STGB;

        #pragma unroll
        for (int ks = 0; ks < 2; ks++) {
            const uint32_t ko = (uint32_t)ks * 32;   // k0*4 bytes
            uint32_t af[4][4], bf[4][2];
            #pragma unroll
            for (int mi = 0; mi < 4; mi++)
                ldsm4(af[mi][0], af[mi][1], af[mi][2], af[mi][3],
                      aS + (uint32_t)mi * (16 * LDP * 4) + ko);
            #pragma unroll
            for (int p = 0; p < 2; p++)
                ldsm4(bf[2 * p][0], bf[2 * p][1], bf[2 * p + 1][0], bf[2 * p + 1][1],
                      bS + (uint32_t)p * (16 * LDP * 4) + ko);
            #pragma unroll
            for (int mi = 0; mi < 4; mi++)
                #pragma unroll
                for (int ni = 0; ni < 4; ni++)
                    mma8(acc[mi][ni], af[mi], bf[ni]);
        }

        s = (s + 1 >= NSTG) ? 0 : s + 1;
    }

    // ---- epilogue: bias (+sigmoid), float2 stores ----
    #pragma unroll
    for (int ni = 0; ni < 4; ni++) {
        const int bcol = bnb * BN + wn + ni * 8 + lc * 2;     // into bias array
        const int gc   = ncol * BN + wn + ni * 8 + lc * 2;    // into C
        const float b0 = bias[bcol], b1 = bias[bcol + 1];
        #pragma unroll
        for (int mi = 0; mi < 4; mi++) {
            const size_t gr = (size_t)bmb * BM + wm + mi * 16 + lr;
            float v0 = acc[mi][ni][0] + b0;
            float v1 = acc[mi][ni][1] + b1;
            float v2 = acc[mi][ni][2] + b0;
            float v3 = acc[mi][ni][3] + b1;
            if (act) {
                v0 = 1.0f / (1.0f + __expf(-v0));
                v1 = 1.0f / (1.0f + __expf(-v1));
                v2 = 1.0f / (1.0f + __expf(-v2));
                v3 = 1.0f / (1.0f + __expf(-v3));
            }
            *reinterpret_cast<float2*>(C + gr * Dd + gc)       = make_float2(v0, v1);
            *reinterpret_cast<float2*>(C + (gr + 8) * Dd + gc) = make_float2(v2, v3);
        }
    }
    #undef LOAD_STAGE
}

// ---------------------------------------------------------------------------
// Scan phase 1+2 fused (SCALAR lanes, 1024 blocks — R12-proven, unroll 4):
// per-(b,chunk,dblk) local pass; LAST block per (b,dblk) performs the
// 32-chunk serial combine inline. Counters self-reset for graph replay.
// ---------------------------------------------------------------------------
__global__ __launch_bounds__(256, 8)
void scan_p12()
{
    const int xb = blockIdx.x;                 // 0..3
    const int c  = blockIdx.y;                 // 0..31
    const int b  = blockIdx.z;                 // 0..7
    const int d  = xb * 256 + threadIdx.x;
    const size_t base = ((size_t)b * Tt + (size_t)c * CL) * Dd + d;

    float P = 1.0f, S = 0.0f;
    #pragma unroll 4
    for (int t = 0; t < CL; ++t) {
        const float gg = sc_g[base + (size_t)t * Dd];
        const float uu = sc_u[base + (size_t)t * Dd];
        S = fmaf(gg, S, (1.0f - gg) * uu);
        P *= gg;
    }
    const int idx = (b * NC + c) * Dd + d;
    sc_P[idx] = P;
    sc_S[idx] = S;

    __threadfence();
    __shared__ int lastf;
    if (threadIdx.x == 0)
        lastf = (atomicAdd(&sc_cnt[b * 4 + xb], 1) == NC - 1) ? 1 : 0;
    __syncthreads();

    if (lastf) {
        if (threadIdx.x == 0) sc_cnt[b * 4 + xb] = 0;   // reset for next replay
        __threadfence();
        float carry = 0.0f;
        #pragma unroll
        for (int c2 = 0; c2 < NC; ++c2) {
            const int k = (b * NC + c2) * Dd + d;
            sc_C[k] = carry;
            carry = fmaf(sc_P[k], carry, sc_S[k]);
        }
    }
}

// ---------------------------------------------------------------------------
// Scan phase 3 (SCALAR lanes, 1024 blocks — R12-proven, unroll 4): replay
// each chunk from its carry-in, writing tf32-rounded h (feeds only GEMM3).
// ---------------------------------------------------------------------------
__global__ void scan_phase3()
{
    const int d = blockIdx.x * blockDim.x + threadIdx.x;
    const int c = blockIdx.y;
    const int b = blockIdx.z;
    const size_t base = ((size_t)b * Tt + (size_t)c * CL) * Dd + d;

    float h = sc_C[(b * NC + c) * Dd + d];
    #pragma unroll 4
    for (int t = 0; t < CL; ++t) {
        const float gg = sc_g[base + (size_t)t * Dd];
        const float uu = sc_u[base + (size_t)t * Dd];
        h = fmaf(gg, h, (1.0f - gg) * uu);
        sc_h[base + (size_t)t * Dd] = f2tf_f(h);
    }
}

// ---------------------------------------------------------------------------
extern "C" void kernel_launch(void* const* d_in, const int* in_sizes, int n_in,
                              void* d_out, int out_size)
{
    (void)in_sizes; (void)n_in; (void)out_size;

    const float* x  = (const float*)d_in[0];
    const float* Wi = (const float*)d_in[1];
    const float* bi = (const float*)d_in[2];
    const float* Wg = (const float*)d_in[3];
    const float* bg = (const float*)d_in[4];
    const float* Wo = (const float*)d_in[5];
    const float* bo = (const float*)d_in[6];
    float* out = (float*)d_out;

    float *u, *g, *h, *xt, *wt, *bc;
    cudaGetSymbolAddress((void**)&u,  sc_u);
    cudaGetSymbolAddress((void**)&g,  sc_g);
    cudaGetSymbolAddress((void**)&h,  sc_h);
    cudaGetSymbolAddress((void**)&xt, sc_xt);
    cudaGetSymbolAddress((void**)&wt, sc_wt);
    cudaGetSymbolAddress((void**)&bc, sc_bc);
    float* wto = wt + 2 * (size_t)Dd * Dd;

    cudaFuncSetAttribute(gemm_tc, cudaFuncAttributeMaxDynamicSharedMemorySize, SMEM_BYTES);

    // unified prologue: round x + all weights, concat biases — ONE launch
    round_all_k<<<XBLK + 3 * WBLK + 1, 256>>>(
        (const float4*)x, (const float4*)Wi, (const float4*)Wg, (const float4*)Wo,
        (const float4*)bi, (const float4*)bg,
        (float4*)xt, (float4*)wt, (float4*)bc);

    // fused u+g GEMM: W = Wi||Wg (2048 rows), bias = bi||bg
    gemm_tc<<<dim3(16, Mtot / BM), 256, SMEM_BYTES>>>(xt, wt, bc, u, g, 1);

    scan_p12<<<dim3(4, NC, Bb), 256>>>();
    scan_phase3<<<dim3(4, NC, Bb), 256>>>();

    gemm_tc<<<dim3(8, Mtot / BM), 256, SMEM_BYTES>>>(h, wto, bo, out, nullptr, 0);
}

// round 17
// speedup vs baseline: 1.0308x; 1.0049x over previous
#include <cuda_runtime.h>
#include <math.h>
#include <stdint.h>

// Problem constants (fixed by the reference: B=8, T=4096, D=1024)
constexpr int Bb   = 8;
constexpr int Tt   = 4096;
constexpr int Dd   = 1024;
constexpr int Mtot = Bb * Tt;          // 32768 rows
constexpr int NC   = 32;               // scan chunks (proven)
constexpr int CL   = Tt / NC;          // 128 steps per chunk

// Scratch (device globals — no allocations allowed in kernel_launch)
__device__ float sc_u[(size_t)Mtot * Dd];
__device__ float sc_g[(size_t)Mtot * Dd];
__device__ float sc_h[(size_t)Mtot * Dd];    // written tf32-rounded by scan p3
__device__ float sc_xt[(size_t)Mtot * Dd];   // x rounded to tf32 bits
__device__ float sc_wt[3][(size_t)Dd * Dd];  // Wi/Wg/Wo rounded (contiguous!)
__device__ float sc_bc[2 * Dd];              // concat(bi, bg)
__device__ float sc_P[Bb * NC * Dd];
__device__ float sc_S[Bb * NC * Dd];
__device__ float sc_C[Bb * NC * Dd];
__device__ int   sc_cnt[Bb * 4];             // p1->p2 fusion counters (self-reset)

__device__ __forceinline__ uint32_t f2tf(float x) {
    uint32_t r;
    asm("cvt.rna.tf32.f32 %0, %1;" : "=r"(r) : "f"(x));
    return r;
}
__device__ __forceinline__ float f2tf_f(float x) { return __uint_as_float(f2tf(x)); }

// ---------------------------------------------------------------------------
// Unified prologue rounding: ONE launch rounds x (blocks [0,4096)), the three
// weight matrices (blocks [4096,4864), 256 each) and copies the bias concat
// (block 4864). All sections are DRAM-parallel.
// ---------------------------------------------------------------------------
constexpr int XBLK = 4096;
constexpr int WBLK = 256;

__global__ void round_all_k(const float4* __restrict__ x,
                            const float4* __restrict__ w0,
                            const float4* __restrict__ w1,
                            const float4* __restrict__ w2,
                            const float4* __restrict__ b0,
                            const float4* __restrict__ b1,
                            float4* __restrict__ xt,
                            float4* __restrict__ wt,
                            float4* __restrict__ bc)
{
    const int bx = blockIdx.x;
    const int n4w = Dd * Dd / 4;

    if (bx < XBLK) {                       // ---- x rounding ----
        const int n4 = Mtot * Dd / 4;
        const int stride = XBLK * 256;
        for (int i = bx * 256 + threadIdx.x; i < n4; i += stride) {
            float4 v = x[i];
            xt[i] = make_float4(f2tf_f(v.x), f2tf_f(v.y), f2tf_f(v.z), f2tf_f(v.w));
        }
    } else if (bx < XBLK + 3 * WBLK) {     // ---- weight rounding ----
        const int wsel = (bx - XBLK) / WBLK;          // 0..2
        const int wb   = (bx - XBLK) % WBLK;          // block within matrix
        const float4* in = (wsel == 0) ? w0 : (wsel == 1) ? w1 : w2;
        float4* out = wt + (size_t)wsel * n4w;
        const int stride = WBLK * 256;
        for (int i = wb * 256 + threadIdx.x; i < n4w; i += stride) {
            float4 v = in[i];
            out[i] = make_float4(f2tf_f(v.x), f2tf_f(v.y), f2tf_f(v.z), f2tf_f(v.w));
        }
    } else {                               // ---- bias concat ----
        for (int i = threadIdx.x; i < Dd / 4; i += blockDim.x) {
            bc[i] = b0[i];
            bc[Dd / 4 + i] = b1[i];
        }
    }
}

// ===========================================================================
// tf32 mma.sync GEMM on PRE-ROUNDED operands (proven, unchanged):
// dual=1: W has 2048 rows (Wi||Wg), bias 2048; bn<8 -> C0 (no act),
//         bn>=8 -> C1 (sigmoid). dual=0: classic 1024-row GEMM into C0.
// CTA 128x128, BK=16, 8 warps @ 64x32, 3-stage cp.async, one barrier/chunk,
// ldmatrix fragments, zero mainloop cvt.
// ===========================================================================
constexpr int BM = 128, BN = 128, BK = 16;
constexpr int NCHUNK = Dd / BK;        // 64
constexpr int LDP    = BK + 4;         // padded row stride (floats)
constexpr int STGB   = BM * LDP * 4;   // stage bytes per matrix (10240)
constexpr int NSTG   = 3;
constexpr int SMEM_BYTES = 2 * NSTG * STGB;   // 61440

__device__ __forceinline__ uint32_t smem_u32(const void* p) {
    uint32_t a;
    asm("{ .reg .u64 t; cvta.to.shared.u64 t, %1; cvt.u32.u64 %0, t; }"
        : "=r"(a) : "l"(p));
    return a;
}
__device__ __forceinline__ void cp16(uint32_t s, const void* g) {
    asm volatile("cp.async.cg.shared.global [%0], [%1], 16;" :: "r"(s), "l"(g));
}
__device__ __forceinline__ void ldsm4(uint32_t& r0, uint32_t& r1, uint32_t& r2,
                                      uint32_t& r3, uint32_t addr) {
    asm volatile("ldmatrix.sync.aligned.m8n8.x4.shared.b16 {%0,%1,%2,%3}, [%4];"
                 : "=r"(r0), "=r"(r1), "=r"(r2), "=r"(r3) : "r"(addr));
}
__device__ __forceinline__ void mma8(float* d, const uint32_t* a, const uint32_t* b) {
    asm volatile(
        "mma.sync.aligned.m16n8k8.row.col.f32.tf32.tf32.f32 "
        "{%0,%1,%2,%3}, {%4,%5,%6,%7}, {%8,%9}, {%0,%1,%2,%3};"
        : "+f"(d[0]), "+f"(d[1]), "+f"(d[2]), "+f"(d[3])
        : "r"(a[0]), "r"(a[1]), "r"(a[2]), "r"(a[3]), "r"(b[0]), "r"(b[1]));
}

__global__ __launch_bounds__(256, 2)
void gemm_tc(const float* __restrict__ A, const float* __restrict__ W,
             const float* __restrict__ bias, float* __restrict__ C0,
             float* __restrict__ C1, int dual)
{
    extern __shared__ float dynsm[];
    float* Asm = dynsm;                         // [NSTG][BM][LDP]
    float* Bsm = dynsm + NSTG * BM * LDP;       // [NSTG][BN][LDP]

    const int tid  = threadIdx.x;
    const int wid  = tid >> 5;
    const int lane = tid & 31;
    const int lr   = lane >> 2;          // 0..7
    const int lc   = lane & 3;           // 0..3
    const int bnb  = blockIdx.x;         // N tile (0..7 or 0..15)
    const int bmb  = blockIdx.y;         // M tile (0..255)

    const int act  = dual && (bnb >= 8);
    float* C       = (dual && bnb >= 8) ? C1 : C0;
    const int ncol = dual ? (bnb & 7) : bnb;     // output column tile

    const int wm = (wid >> 2) * 64;      // warp M offset in tile
    const int wn = (wid & 3) * 32;       // warp N offset in tile

    // ---- cp.async loader mapping ----
    const int r0 = tid >> 2,  q0 = tid & 3;
    const int r1 = r0 + 64;
    const float4* A4 = reinterpret_cast<const float4*>(A) + ((size_t)bmb * BM) * (Dd / 4);
    const float4* B4 = reinterpret_cast<const float4*>(W) + ((size_t)bnb * BN) * (Dd / 4);

    const uint32_t abase = smem_u32(Asm);
    const uint32_t bbase = smem_u32(Bsm);

    uint32_t sA0[NSTG], sA1[NSTG], sB0[NSTG], sB1[NSTG];
    #pragma unroll
    for (int s = 0; s < NSTG; s++) {
        sA0[s] = abase + ((s * BM + r0) * LDP + q0 * 4) * 4;
        sA1[s] = abase + ((s * BM + r1) * LDP + q0 * 4) * 4;
        sB0[s] = bbase + ((s * BN + r0) * LDP + q0 * 4) * 4;
        sB1[s] = bbase + ((s * BN + r1) * LDP + q0 * 4) * 4;
    }

    // ---- ldmatrix per-lane base addresses (stage 0) ----
    const uint32_t aFrag = abase + (((wm + (lane & 15)) * LDP + (lane >> 4) * 4) * 4);
    const uint32_t bFrag = bbase + (((wn + (lane & 7) + (lane >> 4) * 8) * LDP
                                     + ((lane >> 3) & 1) * 4) * 4);

    #define LOAD_STAGE(c, s) do {                                            \
        const float4* ga0 = A4 + (size_t)r0 * (Dd / 4) + (c) * 4 + q0;        \
        const float4* ga1 = A4 + (size_t)r1 * (Dd / 4) + (c) * 4 + q0;        \
        const float4* gb0 = B4 + (size_t)r0 * (Dd / 4) + (c) * 4 + q0;        \
        const float4* gb1 = B4 + (size_t)r1 * (Dd / 4) + (c) * 4 + q0;        \
        cp16(sA0[s], ga0); cp16(sA1[s], ga1);                                 \
        cp16(sB0[s], gb0); cp16(sB1[s], gb1);                                 \
        asm volatile("cp.async.commit_group;");                               \
    } while (0)

    float acc[4][4][4] = {};

    LOAD_STAGE(0, 0);
    LOAD_STAGE(1, 1);

    int s = 0;                 // stage of chunk c
    for (int c = 0; c < NCHUNK; c++) {
        if (c + 1 < NCHUNK) asm volatile("cp.async.wait_group 1;" ::: "memory");
        else                asm volatile("cp.async.wait_group 0;" ::: "memory");
        __syncthreads();   // stage c visible; stage c-1 consumed everywhere

        if (c + 2 < NCHUNK) {
            const int sn = (s + 2 >= NSTG) ? s + 2 - NSTG : s + 2;
            LOAD_STAGE(c + 2, sn);
        }

        const uint32_t aS = aFrag + (uint32_t)s * STGB;
        const uint32_t bS = bFrag + (uint32_t)s * STGB;

        #pragma unroll
        for (int ks = 0; ks < 2; ks++) {
            const uint32_t ko = (uint32_t)ks * 32;   // k0*4 bytes
            uint32_t af[4][4], bf[4][2];
            #pragma unroll
            for (int mi = 0; mi < 4; mi++)
                ldsm4(af[mi][0], af[mi][1], af[mi][2], af[mi][3],
                      aS + (uint32_t)mi * (16 * LDP * 4) + ko);
            #pragma unroll
            for (int p = 0; p < 2; p++)
                ldsm4(bf[2 * p][0], bf[2 * p][1], bf[2 * p + 1][0], bf[2 * p + 1][1],
                      bS + (uint32_t)p * (16 * LDP * 4) + ko);
            #pragma unroll
            for (int mi = 0; mi < 4; mi++)
                #pragma unroll
                for (int ni = 0; ni < 4; ni++)
                    mma8(acc[mi][ni], af[mi], bf[ni]);
        }

        s = (s + 1 >= NSTG) ? 0 : s + 1;
    }

    // ---- epilogue: bias (+sigmoid), float2 stores ----
    #pragma unroll
    for (int ni = 0; ni < 4; ni++) {
        const int bcol = bnb * BN + wn + ni * 8 + lc * 2;     // into bias array
        const int gc   = ncol * BN + wn + ni * 8 + lc * 2;    // into C
        const float b0 = bias[bcol], b1 = bias[bcol + 1];
        #pragma unroll
        for (int mi = 0; mi < 4; mi++) {
            const size_t gr = (size_t)bmb * BM + wm + mi * 16 + lr;
            float v0 = acc[mi][ni][0] + b0;
            float v1 = acc[mi][ni][1] + b1;
            float v2 = acc[mi][ni][2] + b0;
            float v3 = acc[mi][ni][3] + b1;
            if (act) {
                v0 = 1.0f / (1.0f + __expf(-v0));
                v1 = 1.0f / (1.0f + __expf(-v1));
                v2 = 1.0f / (1.0f + __expf(-v2));
                v3 = 1.0f / (1.0f + __expf(-v3));
            }
            *reinterpret_cast<float2*>(C + gr * Dd + gc)       = make_float2(v0, v1);
            *reinterpret_cast<float2*>(C + (gr + 8) * Dd + gc) = make_float2(v2, v3);
        }
    }
    #undef LOAD_STAGE
}

// ---------------------------------------------------------------------------
// Scan phase 1+2 fused (SCALAR lanes, 1024 blocks — proven, unroll 4), with
// evict-first loads (__ldcs): g,u have no L2 reuse within this kernel and
// won't survive 384MB of traffic until phase3 anyway.
// ---------------------------------------------------------------------------
__global__ __launch_bounds__(256, 8)
void scan_p12()
{
    const int xb = blockIdx.x;                 // 0..3
    const int c  = blockIdx.y;                 // 0..31
    const int b  = blockIdx.z;                 // 0..7
    const int d  = xb * 256 + threadIdx.x;
    const size_t base = ((size_t)b * Tt + (size_t)c * CL) * Dd + d;

    float P = 1.0f, S = 0.0f;
    #pragma unroll 4
    for (int t = 0; t < CL; ++t) {
        const float gg = __ldcs(&sc_g[base + (size_t)t * Dd]);
        const float uu = __ldcs(&sc_u[base + (size_t)t * Dd]);
        S = fmaf(gg, S, (1.0f - gg) * uu);
        P *= gg;
    }
    const int idx = (b * NC + c) * Dd + d;
    sc_P[idx] = P;
    sc_S[idx] = S;

    __threadfence();
    __shared__ int lastf;
    if (threadIdx.x == 0)
        lastf = (atomicAdd(&sc_cnt[b * 4 + xb], 1) == NC - 1) ? 1 : 0;
    __syncthreads();

    if (lastf) {
        if (threadIdx.x == 0) sc_cnt[b * 4 + xb] = 0;   // reset for next replay
        __threadfence();
        float carry = 0.0f;
        #pragma unroll
        for (int c2 = 0; c2 < NC; ++c2) {
            const int k = (b * NC + c2) * Dd + d;
            sc_C[k] = carry;
            carry = fmaf(sc_P[k], carry, sc_S[k]);
        }
    }
}

// ---------------------------------------------------------------------------
// Scan phase 3 (SCALAR lanes, 1024 blocks — proven, unroll 4): replay each
// chunk from its carry-in, writing tf32-rounded h. Final reads of g,u use
// __ldcs (dead after this); h written with __stcs (consumed a kernel later,
// won't survive in L2 — avoid write-allocate thrash).
// ---------------------------------------------------------------------------
__global__ void scan_phase3()
{
    const int d = blockIdx.x * blockDim.x + threadIdx.x;
    const int c = blockIdx.y;
    const int b = blockIdx.z;
    const size_t base = ((size_t)b * Tt + (size_t)c * CL) * Dd + d;

    float h = sc_C[(b * NC + c) * Dd + d];
    #pragma unroll 4
    for (int t = 0; t < CL; ++t) {
        const float gg = __ldcs(&sc_g[base + (size_t)t * Dd]);
        const float uu = __ldcs(&sc_u[base + (size_t)t * Dd]);
        h = fmaf(gg, h, (1.0f - gg) * uu);
        __stcs(&sc_h[base + (size_t)t * Dd], f2tf_f(h));
    }
}

// ---------------------------------------------------------------------------
extern "C" void kernel_launch(void* const* d_in, const int* in_sizes, int n_in,
                              void* d_out, int out_size)
{
    (void)in_sizes; (void)n_in; (void)out_size;

    const float* x  = (const float*)d_in[0];
    const float* Wi = (const float*)d_in[1];
    const float* bi = (const float*)d_in[2];
    const float* Wg = (const float*)d_in[3];
    const float* bg = (const float*)d_in[4];
    const float* Wo = (const float*)d_in[5];
    const float* bo = (const float*)d_in[6];
    float* out = (float*)d_out;

    float *u, *g, *h, *xt, *wt, *bc;
    cudaGetSymbolAddress((void**)&u,  sc_u);
    cudaGetSymbolAddress((void**)&g,  sc_g);
    cudaGetSymbolAddress((void**)&h,  sc_h);
    cudaGetSymbolAddress((void**)&xt, sc_xt);
    cudaGetSymbolAddress((void**)&wt, sc_wt);
    cudaGetSymbolAddress((void**)&bc, sc_bc);
    float* wto = wt + 2 * (size_t)Dd * Dd;

    cudaFuncSetAttribute(gemm_tc, cudaFuncAttributeMaxDynamicSharedMemorySize, SMEM_BYTES);

    // unified prologue: round x + all weights, concat biases — ONE launch
    round_all_k<<<XBLK + 3 * WBLK + 1, 256>>>(
        (const float4*)x, (const float4*)Wi, (const float4*)Wg, (const float4*)Wo,
        (const float4*)bi, (const float4*)bg,
        (float4*)xt, (float4*)wt, (float4*)bc);

    // fused u+g GEMM: W = Wi||Wg (2048 rows), bias = bi||bg
    gemm_tc<<<dim3(16, Mtot / BM), 256, SMEM_BYTES>>>(xt, wt, bc, u, g, 1);

    scan_p12<<<dim3(4, NC, Bb), 256>>>();
    scan_phase3<<<dim3(4, NC, Bb), 256>>>();

    gemm_tc<<<dim3(8, Mtot / BM), 256, SMEM_BYTES>>>(h, wto, bo, out, nullptr, 0);
}